// round 8
// baseline (speedup 1.0000x reference)
#include <cuda_runtime.h>
#include <stdint.h>
#include <math.h>

#define H   256
#define EMAX 200000

// 204.8 MB scratch for the scatter-add target (allocation-free rule: static __device__).
__device__ float g_agg[(size_t)EMAX * H];
// Index dtype mode: 1 = int64, 0 = int32.
__device__ int g_idx_mode;

__device__ __forceinline__ void mma_tf32(float c[4], const uint32_t a[4], const uint32_t b[2]) {
    asm volatile(
        "mma.sync.aligned.m16n8k8.row.col.f32.tf32.tf32.f32 "
        "{%0,%1,%2,%3},{%4,%5,%6,%7},{%8,%9},{%0,%1,%2,%3};"
        : "+f"(c[0]), "+f"(c[1]), "+f"(c[2]), "+f"(c[3])
        : "r"(a[0]), "r"(a[1]), "r"(a[2]), "r"(a[3]), "r"(b[0]), "r"(b[1]));
}

__device__ __forceinline__ float sigmoidf_(float x) {
    return 1.0f / (1.0f + __expf(-x));
}

__device__ __forceinline__ void cp16(uint32_t dst, const void* src, bool pred) {
    int sz = pred ? 16 : 0;
    asm volatile("cp.async.cg.shared.global [%0], [%1], 16, %2;\n"
                 :: "r"(dst), "l"(src), "r"(sz));
}
__device__ __forceinline__ void cp_commit() {
    asm volatile("cp.async.commit_group;\n");
}
template <int N>
__device__ __forceinline__ void cp_wait() {
    asm volatile("cp.async.wait_group %0;\n" :: "n"(N));
}

// ============================================================================
// Kernel A: detect index dtype (int64 vs int32 materialization of edge_index).
// ============================================================================
__global__ void detect_idx_kernel(const int* __restrict__ idx32)
{
    __shared__ int ored[256];
    int t = threadIdx.x;
    ored[t] = idx32[2 * t + 1];
    __syncthreads();
    for (int s = 128; s > 0; s >>= 1) {
        if (t < s) ored[t] |= ored[t + s];
        __syncthreads();
    }
    if (t == 0) g_idx_mode = (ored[0] == 0) ? 1 : 0;
}

// ============================================================================
// Kernel 0: zero the aggregation scratch.
// ============================================================================
__global__ void zero_agg_kernel(int total4)
{
    float4* p = reinterpret_cast<float4*>(g_agg);
    int idx = blockIdx.x * blockDim.x + threadIdx.x;
    int stride = gridDim.x * blockDim.x;
    float4 z = make_float4(0.f, 0.f, 0.f, 0.f);
    for (int i = idx; i < total4; i += stride) p[i] = z;
}

// ============================================================================
// Kernel 1 (UNCHANGED from round 7): relu(X @ W_msg^T + b) + atomic scatter.
// kchunk 32, 2-stage cp.async, y-fast grid (4 n-tiles consecutive).
// ============================================================================
#define MS_STAGE 6912

__global__ __launch_bounds__(256)
void msg_scatter_kernel(const float* __restrict__ X,
                        const void* __restrict__ eidx,
                        const float* __restrict__ W,
                        const float* __restrict__ bias,
                        int E)
{
    extern __shared__ uint32_t dsm[];
    __shared__ int dsts[128];

    const int tid  = threadIdx.x;
    const int lane = tid & 31;
    const int wid  = tid >> 5;
    const int wm   = wid & 3;
    const int wn   = wid >> 2;
    const int row0 = (int)(blockIdx.x >> 2) * 128;
    const int n0   = (int)(blockIdx.x & 3) * 64;
    const uint32_t sbase = (uint32_t)__cvta_generic_to_shared(dsm);

    if (tid < 128) {
        int r = row0 + tid;
        int d = -1;
        if (r < E) {
            d = g_idx_mode ? (int)((const long long*)eidx)[(size_t)E + r]
                           : ((const int*)eidx)[(size_t)E + r];
            if (d < 0 || d >= E) d = -1;
        }
        dsts[tid] = d;
    }

    const int lr  = tid >> 3;
    const int lc4 = (tid & 7) * 4;

    auto load_stage = [&](int st, int k0) {
        uint32_t sb = sbase + st * (MS_STAGE * 4);
#pragma unroll
        for (int p = 0; p < 4; p++) {
            int r  = p * 32 + lr;
            int gr = row0 + r;
            cp16(sb + (r * 36 + lc4) * 4, X + (size_t)gr * H + k0 + lc4, gr < E);
        }
#pragma unroll
        for (int p = 0; p < 2; p++) {
            int r = p * 32 + lr;
            cp16(sb + (4608 + r * 36 + lc4) * 4,
                 W + (size_t)(n0 + r) * H + k0 + lc4, true);
        }
        cp_commit();
    };

    float acc[2][4][4];
#pragma unroll
    for (int i = 0; i < 2; i++)
#pragma unroll
        for (int j = 0; j < 4; j++)
#pragma unroll
            for (int k = 0; k < 4; k++) acc[i][j][k] = 0.0f;

    load_stage(0, 0);

    for (int kc = 0; kc < 8; kc++) {
        if (kc < 7) { load_stage((kc + 1) & 1, (kc + 1) * 32); cp_wait<1>(); }
        else        { cp_wait<0>(); }
        __syncthreads();

        const uint32_t* As = dsm + (kc & 1) * MS_STAGE;
        const uint32_t* Bs = As + 4608;

#pragma unroll
        for (int ks = 0; ks < 4; ks++) {
            int kk = ks * 8;
            uint32_t a[2][4], b[4][2];
#pragma unroll
            for (int mi = 0; mi < 2; mi++) {
                int r = wm * 32 + mi * 16 + (lane >> 2);
                a[mi][0] = As[r * 36 + kk + (lane & 3)];
                a[mi][1] = As[(r + 8) * 36 + kk + (lane & 3)];
                a[mi][2] = As[r * 36 + kk + 4 + (lane & 3)];
                a[mi][3] = As[(r + 8) * 36 + kk + 4 + (lane & 3)];
            }
#pragma unroll
            for (int ni = 0; ni < 4; ni++) {
                int nb = wn * 32 + ni * 8 + (lane >> 2);
                b[ni][0] = Bs[nb * 36 + kk + (lane & 3)];
                b[ni][1] = Bs[nb * 36 + kk + 4 + (lane & 3)];
            }
#pragma unroll
            for (int mi = 0; mi < 2; mi++)
#pragma unroll
                for (int ni = 0; ni < 4; ni++)
                    mma_tf32(acc[mi][ni], a[mi], b[ni]);
        }
        __syncthreads();
    }

#pragma unroll
    for (int mi = 0; mi < 2; mi++) {
#pragma unroll
        for (int half = 0; half < 2; half++) {
            int rl = wm * 32 + mi * 16 + (lane >> 2) + half * 8;
            int d  = dsts[rl];
            if (d < 0) continue;
            size_t base = (size_t)d * H;
#pragma unroll
            for (int ni = 0; ni < 4; ni++) {
                int col  = n0 + wn * 32 + ni * 8 + 2 * (lane & 3);
                float v0 = fmaxf(acc[mi][ni][half * 2 + 0] + __ldg(&bias[col]), 0.0f);
                float v1 = fmaxf(acc[mi][ni][half * 2 + 1] + __ldg(&bias[col + 1]), 0.0f);
                atomicAdd(&g_agg[base + col],     v0);
                atomicAdd(&g_agg[base + col + 1], v1);
            }
        }
    }
}

// ============================================================================
// Kernel 2: GRU fused GEMMs — warp-tile 64x32, 6 warps (192 threads).
// Block = 64 rows x 32 h-cols x 6 gates. Warp g owns gate g over ALL 64 rows:
// per ks, b-fragments (8 LDS) are reused across 4 row-slabs (16 MMAs).
// LDS/MMA = 1.5 (was 2.0); block fragment reads 72KB vs 96KB per chunk.
// kchunk 32, 2-stage cp.async, y-fast grid. Stage layout identical to r7:
// uAagg[2304]@0, uAx[2304]@2304, uB[6912]@4608, stage=11520 words.
// gbuf (64x192 fp32 = 48KB) aliases the stage ring after the mainloop.
// ============================================================================
#define GK_STAGE 11520
#define GK_THREADS 192

__global__ __launch_bounds__(GK_THREADS, 2)
void gru_kernel(const float* __restrict__ X,
                const float* __restrict__ Wih,
                const float* __restrict__ Whh,
                const float* __restrict__ bih,
                const float* __restrict__ bhh,
                float* __restrict__ out,
                int E)
{
    extern __shared__ uint32_t dsm[];
    float* gbuf = reinterpret_cast<float*>(dsm);

    const int tid  = threadIdx.x;
    const int lane = tid & 31;
    const int g    = tid >> 5;                    // warp = gate 0..5
    const int row0 = (int)(blockIdx.x >> 3) * 64; // y-fast: low 3 bits = n-tile
    const int n0   = (int)(blockIdx.x & 7) * 32;
    const uint32_t sbase = (uint32_t)__cvta_generic_to_shared(dsm);

    auto load_stage = [&](int st, int k0) {
        uint32_t sb = sbase + st * (GK_STAGE * 4);
        // A tiles: agg (64x32) then X (64x32): 1024 16B-chunks
        for (int f = tid; f < 1024; f += GK_THREADS) {
            int which = f >> 9;
            int rem   = f & 511;
            int r     = rem >> 3;
            int c4    = (rem & 7) * 4;
            int gr    = row0 + r;
            const float* src = which ? (X + (size_t)gr * H)
                                     : (g_agg + (size_t)gr * H);
            cp16(sb + ((which ? 2304 : 0) + r * 36 + c4) * 4,
                 src + k0 + c4, gr < E);
        }
        // 6 weight tiles (32x32 each): 1536 16B-chunks (8/thread)
#pragma unroll
        for (int q = 0; q < 8; q++) {
            int f   = tid + q * GK_THREADS;
            int g2  = f >> 8;
            int rem = f & 255;
            int r   = rem >> 3;
            int c4  = (rem & 7) * 4;
            int gate = (g2 < 3) ? g2 : (g2 - 3);
            const float* Wsrc = (g2 < 3) ? Wih : Whh;
            cp16(sb + (4608 + (g2 * 32 + r) * 36 + c4) * 4,
                 Wsrc + (size_t)(gate * H + n0 + r) * H + k0 + c4, true);
        }
        cp_commit();
    };

    float acc[4][4][4];
#pragma unroll
    for (int i = 0; i < 4; i++)
#pragma unroll
        for (int j = 0; j < 4; j++)
#pragma unroll
            for (int k = 0; k < 4; k++) acc[i][j][k] = 0.0f;

    load_stage(0, 0);

    for (int kc = 0; kc < 8; kc++) {
        if (kc < 7) { load_stage((kc + 1) & 1, (kc + 1) * 32); cp_wait<1>(); }
        else        { cp_wait<0>(); }
        __syncthreads();

        const uint32_t* S  = dsm + (kc & 1) * GK_STAGE;
        const uint32_t* Aw = (g < 3) ? S : (S + 2304);
        const uint32_t* uB = S + 4608;

#pragma unroll
        for (int ks = 0; ks < 4; ks++) {
            int kk = ks * 8;
            // b fragments: loaded once, reused by all 4 row-slabs
            uint32_t b[4][2];
#pragma unroll
            for (int ni = 0; ni < 4; ni++) {
                int nb = g * 32 + ni * 8 + (lane >> 2);
                b[ni][0] = uB[nb * 36 + kk + (lane & 3)];
                b[ni][1] = uB[nb * 36 + kk + 4 + (lane & 3)];
            }
#pragma unroll
            for (int mi = 0; mi < 4; mi++) {
                int r = mi * 16 + (lane >> 2);
                uint32_t a[4];
                a[0] = Aw[r * 36 + kk + (lane & 3)];
                a[1] = Aw[(r + 8) * 36 + kk + (lane & 3)];
                a[2] = Aw[r * 36 + kk + 4 + (lane & 3)];
                a[3] = Aw[(r + 8) * 36 + kk + 4 + (lane & 3)];
#pragma unroll
                for (int ni = 0; ni < 4; ni++)
                    mma_tf32(acc[mi][ni], a, b[ni]);
            }
        }
        __syncthreads();
    }

    // ---- dump accumulators: gbuf[r][g*32 + c], row stride 192 ----
#pragma unroll
    for (int mi = 0; mi < 4; mi++) {
        int r = mi * 16 + (lane >> 2);
#pragma unroll
        for (int ni = 0; ni < 4; ni++) {
            int c = g * 32 + ni * 8 + 2 * (lane & 3);
            gbuf[r * 192 + c]           = acc[mi][ni][0];
            gbuf[r * 192 + c + 1]       = acc[mi][ni][1];
            gbuf[(r + 8) * 192 + c]     = acc[mi][ni][2];
            gbuf[(r + 8) * 192 + c + 1] = acc[mi][ni][3];
        }
    }
    __syncthreads();

    // ---- GRU gate math + output (2048 elems / 192 threads) ----
    for (int idx = tid; idx < 64 * 32; idx += GK_THREADS) {
        int r  = idx >> 5;
        int c  = idx & 31;
        int gr = row0 + r;
        if (gr >= E) continue;
        int gc = n0 + c;
        const float* gr_ = &gbuf[r * 192];
        float i_r = gr_[c]       + __ldg(&bih[gc]);
        float i_z = gr_[32 + c]  + __ldg(&bih[H + gc]);
        float i_n = gr_[64 + c]  + __ldg(&bih[2 * H + gc]);
        float h_r = gr_[96 + c]  + __ldg(&bhh[gc]);
        float h_z = gr_[128 + c] + __ldg(&bhh[H + gc]);
        float h_n = gr_[160 + c] + __ldg(&bhh[2 * H + gc]);

        float rg = sigmoidf_(i_r + h_r);
        float z  = sigmoidf_(i_z + h_z);
        float n  = tanhf(i_n + rg * h_n);
        float hp = __ldg(&X[(size_t)gr * H + gc]);
        out[(size_t)gr * H + gc] = (1.0f - z) * n + z * hp;
    }
}

// ============================================================================
extern "C" void kernel_launch(void* const* d_in, const int* in_sizes, int n_in,
                              void* d_out, int out_size)
{
    const float* X   = (const float*)d_in[0];
    const void*  ei  = d_in[1];
    const float* Wm  = (const float*)d_in[2];
    const float* bm  = (const float*)d_in[3];
    const float* Wih = (const float*)d_in[4];
    const float* Whh = (const float*)d_in[5];
    const float* bih = (const float*)d_in[6];
    const float* bhh = (const float*)d_in[7];
    float*       out = (float*)d_out;

    int E = in_sizes[0] / H;

    cudaFuncSetAttribute(msg_scatter_kernel,
                         cudaFuncAttributeMaxDynamicSharedMemorySize, 2 * MS_STAGE * 4);
    cudaFuncSetAttribute(gru_kernel,
                         cudaFuncAttributeMaxDynamicSharedMemorySize, 2 * GK_STAGE * 4);

    detect_idx_kernel<<<1, 256>>>((const int*)ei);
    zero_agg_kernel<<<4096, 256>>>((E * H) / 4);

    int mrows = (E + 127) / 128;
    msg_scatter_kernel<<<mrows * 4, 256, 2 * MS_STAGE * 4>>>(X, ei, Wm, bm, E);

    int grows = (E + 63) / 64;
    gru_kernel<<<grows * 8, GK_THREADS, 2 * GK_STAGE * 4>>>(X, Wih, Whh, bih, bhh, out, E);
}

// round 9
// speedup vs baseline: 1.1382x; 1.1382x over previous
#include <cuda_runtime.h>
#include <stdint.h>
#include <math.h>

#define H   256
#define EMAX 200000

// 204.8 MB scratch for the scatter-add target (allocation-free rule: static __device__).
__device__ float g_agg[(size_t)EMAX * H];
// Index dtype mode: 1 = int64, 0 = int32.
__device__ int g_idx_mode;

__device__ __forceinline__ void mma_tf32(float c[4], const uint32_t a[4], const uint32_t b[2]) {
    asm volatile(
        "mma.sync.aligned.m16n8k8.row.col.f32.tf32.tf32.f32 "
        "{%0,%1,%2,%3},{%4,%5,%6,%7},{%8,%9},{%0,%1,%2,%3};"
        : "+f"(c[0]), "+f"(c[1]), "+f"(c[2]), "+f"(c[3])
        : "r"(a[0]), "r"(a[1]), "r"(a[2]), "r"(a[3]), "r"(b[0]), "r"(b[1]));
}

// ldmatrix x4: thread L receives, in reg j, matrix j's (row L>>2, 4B-word L&3).
// Lane L supplies the address of matrix (L>>3), row (L&7) — 16B aligned.
__device__ __forceinline__ void ldsm_x4(uint32_t& r0, uint32_t& r1, uint32_t& r2, uint32_t& r3,
                                        uint32_t addr) {
    asm volatile("ldmatrix.sync.aligned.m8n8.x4.shared.b16 {%0,%1,%2,%3}, [%4];"
                 : "=r"(r0), "=r"(r1), "=r"(r2), "=r"(r3) : "r"(addr));
}

__device__ __forceinline__ float sigmoidf_(float x) {
    return 1.0f / (1.0f + __expf(-x));
}

__device__ __forceinline__ void cp16(uint32_t dst, const void* src, bool pred) {
    int sz = pred ? 16 : 0;
    asm volatile("cp.async.cg.shared.global [%0], [%1], 16, %2;\n"
                 :: "r"(dst), "l"(src), "r"(sz));
}
__device__ __forceinline__ void cp_commit() {
    asm volatile("cp.async.commit_group;\n");
}
template <int N>
__device__ __forceinline__ void cp_wait() {
    asm volatile("cp.async.wait_group %0;\n" :: "n"(N));
}

// ============================================================================
// Kernel A: detect index dtype (int64 vs int32 materialization of edge_index).
// ============================================================================
__global__ void detect_idx_kernel(const int* __restrict__ idx32)
{
    __shared__ int ored[256];
    int t = threadIdx.x;
    ored[t] = idx32[2 * t + 1];
    __syncthreads();
    for (int s = 128; s > 0; s >>= 1) {
        if (t < s) ored[t] |= ored[t + s];
        __syncthreads();
    }
    if (t == 0) g_idx_mode = (ored[0] == 0) ? 1 : 0;
}

// ============================================================================
// Kernel 0: zero the aggregation scratch.
// ============================================================================
__global__ void zero_agg_kernel(int total4)
{
    float4* p = reinterpret_cast<float4*>(g_agg);
    int idx = blockIdx.x * blockDim.x + threadIdx.x;
    int stride = gridDim.x * blockDim.x;
    float4 z = make_float4(0.f, 0.f, 0.f, 0.f);
    for (int i = idx; i < total4; i += stride) p[i] = z;
}

// ============================================================================
// Kernel 1: relu(X @ W_msg^T + b) + atomic scatter. Round-7 structure
// (kchunk 32, 2-stage cp.async, y-fast grid), fragments via ldmatrix.x4.
// ============================================================================
#define MS_STAGE 6912

__global__ __launch_bounds__(256)
void msg_scatter_kernel(const float* __restrict__ X,
                        const void* __restrict__ eidx,
                        const float* __restrict__ W,
                        const float* __restrict__ bias,
                        int E)
{
    extern __shared__ uint32_t dsm[];
    __shared__ int dsts[128];

    const int tid  = threadIdx.x;
    const int lane = tid & 31;
    const int wid  = tid >> 5;
    const int wm   = wid & 3;
    const int wn   = wid >> 2;
    const int row0 = (int)(blockIdx.x >> 2) * 128;
    const int n0   = (int)(blockIdx.x & 3) * 64;
    const uint32_t sbase = (uint32_t)__cvta_generic_to_shared(dsm);

    // ldmatrix lane roles
    const int sub  = lane >> 3;      // matrix index 0..3
    const int lrow = lane & 7;       // row within matrix
    // A matrices: {row+0,row+8} x {k, k+4}:  rowadd=(sub&1)*8, koff=(sub>>1)*4
    const int aoffw = ((sub & 1) * 8 + lrow) * 36 + (sub >> 1) * 4;
    // B matrices: {n+0,n+8} x {k, k+4}:      rowadd=(sub>>1)*8, koff=(sub&1)*4
    const int boffw = ((sub >> 1) * 8 + lrow) * 36 + (sub & 1) * 4;

    if (tid < 128) {
        int r = row0 + tid;
        int d = -1;
        if (r < E) {
            d = g_idx_mode ? (int)((const long long*)eidx)[(size_t)E + r]
                           : ((const int*)eidx)[(size_t)E + r];
            if (d < 0 || d >= E) d = -1;
        }
        dsts[tid] = d;
    }

    const int lr  = tid >> 3;
    const int lc4 = (tid & 7) * 4;

    auto load_stage = [&](int st, int k0) {
        uint32_t sb = sbase + st * (MS_STAGE * 4);
#pragma unroll
        for (int p = 0; p < 4; p++) {
            int r  = p * 32 + lr;
            int gr = row0 + r;
            cp16(sb + (r * 36 + lc4) * 4, X + (size_t)gr * H + k0 + lc4, gr < E);
        }
#pragma unroll
        for (int p = 0; p < 2; p++) {
            int r = p * 32 + lr;
            cp16(sb + (4608 + r * 36 + lc4) * 4,
                 W + (size_t)(n0 + r) * H + k0 + lc4, true);
        }
        cp_commit();
    };

    float acc[2][4][4];
#pragma unroll
    for (int i = 0; i < 2; i++)
#pragma unroll
        for (int j = 0; j < 4; j++)
#pragma unroll
            for (int k = 0; k < 4; k++) acc[i][j][k] = 0.0f;

    load_stage(0, 0);

    for (int kc = 0; kc < 8; kc++) {
        if (kc < 7) { load_stage((kc + 1) & 1, (kc + 1) * 32); cp_wait<1>(); }
        else        { cp_wait<0>(); }
        __syncthreads();

        const uint32_t Au = sbase + ((kc & 1) * MS_STAGE) * 4;
        const uint32_t Bu = Au + 4608 * 4;

#pragma unroll
        for (int ks = 0; ks < 4; ks++) {
            int kk = ks * 8;
            uint32_t a[2][4], b[4][2];
#pragma unroll
            for (int mi = 0; mi < 2; mi++)
                ldsm_x4(a[mi][0], a[mi][1], a[mi][2], a[mi][3],
                        Au + (aoffw + (wm * 32 + mi * 16) * 36 + kk) * 4);
#pragma unroll
            for (int np = 0; np < 2; np++)
                ldsm_x4(b[2 * np][0], b[2 * np][1], b[2 * np + 1][0], b[2 * np + 1][1],
                        Bu + (boffw + (wn * 32 + np * 16) * 36 + kk) * 4);
#pragma unroll
            for (int mi = 0; mi < 2; mi++)
#pragma unroll
                for (int ni = 0; ni < 4; ni++)
                    mma_tf32(acc[mi][ni], a[mi], b[ni]);
        }
        __syncthreads();
    }

#pragma unroll
    for (int mi = 0; mi < 2; mi++) {
#pragma unroll
        for (int half = 0; half < 2; half++) {
            int rl = wm * 32 + mi * 16 + (lane >> 2) + half * 8;
            int d  = dsts[rl];
            if (d < 0) continue;
            size_t base = (size_t)d * H;
#pragma unroll
            for (int ni = 0; ni < 4; ni++) {
                int col  = n0 + wn * 32 + ni * 8 + 2 * (lane & 3);
                float v0 = fmaxf(acc[mi][ni][half * 2 + 0] + __ldg(&bias[col]), 0.0f);
                float v1 = fmaxf(acc[mi][ni][half * 2 + 1] + __ldg(&bias[col + 1]), 0.0f);
                atomicAdd(&g_agg[base + col],     v0);
                atomicAdd(&g_agg[base + col + 1], v1);
            }
        }
    }
}

// ============================================================================
// Kernel 2: GRU fused GEMMs — round-7 shape (384 thr, warp=(row-half, gate),
// kchunk 32, 2-stage, y-fast grid) with ldmatrix.x4 fragment loads:
// per warp-chunk 16 LDSM + 32 MMA (was 96 LDS + 32 MMA).
// ============================================================================
#define GK_STAGE 11520

__global__ __launch_bounds__(384, 2)
void gru_kernel(const float* __restrict__ X,
                const float* __restrict__ Wih,
                const float* __restrict__ Whh,
                const float* __restrict__ bih,
                const float* __restrict__ bhh,
                float* __restrict__ out,
                int E)
{
    extern __shared__ uint32_t dsm[];
    float* gbuf = reinterpret_cast<float*>(dsm);

    const int tid  = threadIdx.x;
    const int lane = tid & 31;
    const int wid  = tid >> 5;
    const int wm   = wid & 1;
    const int g    = wid >> 1;
    const int row0 = (int)(blockIdx.x >> 3) * 64;
    const int n0   = (int)(blockIdx.x & 7) * 32;
    const uint32_t sbase = (uint32_t)__cvta_generic_to_shared(dsm);

    const int sub  = lane >> 3;
    const int lrow = lane & 7;
    const int aoffw = ((sub & 1) * 8 + lrow) * 36 + (sub >> 1) * 4;
    const int boffw = ((sub >> 1) * 8 + lrow) * 36 + (sub & 1) * 4;

    auto load_stage = [&](int st, int k0) {
        uint32_t sb = sbase + st * (GK_STAGE * 4);
        for (int f = tid; f < 1024; f += 384) {
            int which = f >> 9;
            int rem   = f & 511;
            int r     = rem >> 3;
            int c4    = (rem & 7) * 4;
            int gr    = row0 + r;
            const float* src = which ? (X + (size_t)gr * H)
                                     : (g_agg + (size_t)gr * H);
            cp16(sb + ((which ? 2304 : 0) + r * 36 + c4) * 4,
                 src + k0 + c4, gr < E);
        }
#pragma unroll
        for (int q = 0; q < 4; q++) {
            int f   = tid + q * 384;
            int g2  = f >> 8;
            int rem = f & 255;
            int r   = rem >> 3;
            int c4  = (rem & 7) * 4;
            int gate = (g2 < 3) ? g2 : (g2 - 3);
            const float* Wsrc = (g2 < 3) ? Wih : Whh;
            cp16(sb + (4608 + (g2 * 32 + r) * 36 + c4) * 4,
                 Wsrc + (size_t)(gate * H + n0 + r) * H + k0 + c4, true);
        }
        cp_commit();
    };

    float acc[2][4][4];
#pragma unroll
    for (int i = 0; i < 2; i++)
#pragma unroll
        for (int j = 0; j < 4; j++)
#pragma unroll
            for (int k = 0; k < 4; k++) acc[i][j][k] = 0.0f;

    load_stage(0, 0);

    for (int kc = 0; kc < 8; kc++) {
        if (kc < 7) { load_stage((kc + 1) & 1, (kc + 1) * 32); cp_wait<1>(); }
        else        { cp_wait<0>(); }
        __syncthreads();

        const uint32_t Su = sbase + ((kc & 1) * GK_STAGE) * 4;
        const uint32_t Au = Su + ((g < 3) ? 0 : 2304) * 4;
        const uint32_t Bu = Su + 4608 * 4;

#pragma unroll
        for (int ks = 0; ks < 4; ks++) {
            int kk = ks * 8;
            uint32_t a[2][4], b[4][2];
#pragma unroll
            for (int mi = 0; mi < 2; mi++)
                ldsm_x4(a[mi][0], a[mi][1], a[mi][2], a[mi][3],
                        Au + (aoffw + (wm * 32 + mi * 16) * 36 + kk) * 4);
#pragma unroll
            for (int np = 0; np < 2; np++)
                ldsm_x4(b[2 * np][0], b[2 * np][1], b[2 * np + 1][0], b[2 * np + 1][1],
                        Bu + (boffw + (g * 32 + np * 16) * 36 + kk) * 4);
#pragma unroll
            for (int mi = 0; mi < 2; mi++)
#pragma unroll
                for (int ni = 0; ni < 4; ni++)
                    mma_tf32(acc[mi][ni], a[mi], b[ni]);
        }
        __syncthreads();
    }

    // ---- dump accumulators: gbuf[r][g*32 + c], row stride 192 ----
#pragma unroll
    for (int mi = 0; mi < 2; mi++) {
        int r = wm * 32 + mi * 16 + (lane >> 2);
#pragma unroll
        for (int ni = 0; ni < 4; ni++) {
            int c = g * 32 + ni * 8 + 2 * (lane & 3);
            gbuf[r * 192 + c]           = acc[mi][ni][0];
            gbuf[r * 192 + c + 1]       = acc[mi][ni][1];
            gbuf[(r + 8) * 192 + c]     = acc[mi][ni][2];
            gbuf[(r + 8) * 192 + c + 1] = acc[mi][ni][3];
        }
    }
    __syncthreads();

    // ---- GRU gate math + output ----
    for (int idx = tid; idx < 64 * 32; idx += 384) {
        int r  = idx >> 5;
        int c  = idx & 31;
        int gr = row0 + r;
        if (gr >= E) continue;
        int gc = n0 + c;
        const float* gr_ = &gbuf[r * 192];
        float i_r = gr_[c]       + __ldg(&bih[gc]);
        float i_z = gr_[32 + c]  + __ldg(&bih[H + gc]);
        float i_n = gr_[64 + c]  + __ldg(&bih[2 * H + gc]);
        float h_r = gr_[96 + c]  + __ldg(&bhh[gc]);
        float h_z = gr_[128 + c] + __ldg(&bhh[H + gc]);
        float h_n = gr_[160 + c] + __ldg(&bhh[2 * H + gc]);

        float rg = sigmoidf_(i_r + h_r);
        float z  = sigmoidf_(i_z + h_z);
        float n  = tanhf(i_n + rg * h_n);
        float hp = __ldg(&X[(size_t)gr * H + gc]);
        out[(size_t)gr * H + gc] = (1.0f - z) * n + z * hp;
    }
}

// ============================================================================
extern "C" void kernel_launch(void* const* d_in, const int* in_sizes, int n_in,
                              void* d_out, int out_size)
{
    const float* X   = (const float*)d_in[0];
    const void*  ei  = d_in[1];
    const float* Wm  = (const float*)d_in[2];
    const float* bm  = (const float*)d_in[3];
    const float* Wih = (const float*)d_in[4];
    const float* Whh = (const float*)d_in[5];
    const float* bih = (const float*)d_in[6];
    const float* bhh = (const float*)d_in[7];
    float*       out = (float*)d_out;

    int E = in_sizes[0] / H;

    cudaFuncSetAttribute(msg_scatter_kernel,
                         cudaFuncAttributeMaxDynamicSharedMemorySize, 2 * MS_STAGE * 4);
    cudaFuncSetAttribute(gru_kernel,
                         cudaFuncAttributeMaxDynamicSharedMemorySize, 2 * GK_STAGE * 4);

    detect_idx_kernel<<<1, 256>>>((const int*)ei);
    zero_agg_kernel<<<4096, 256>>>((E * H) / 4);

    int mrows = (E + 127) / 128;
    msg_scatter_kernel<<<mrows * 4, 256, 2 * MS_STAGE * 4>>>(X, ei, Wm, bm, E);

    int grows = (E + 63) / 64;
    gru_kernel<<<grows * 8, 384, 2 * GK_STAGE * 4>>>(X, Wih, Whh, bih, bhh, out, E);
}